// round 14
// baseline (speedup 1.0000x reference)
#include <cuda_runtime.h>

#define FULL 0xffffffffu

// LISTA v10 = R9 + (1) merged reduce+neighbor shuffle wave (10 shfl, ONE
// dependent wave; bias stays in prolog registers — R12's regression was the
// in-loop bias, not the merge) + (2) conv channel split across h lanes via
// per-h weight packs (uniform 2-channel code, h=0: ch0+ch1 + cb2, h=1: ch2
// + zero dummy), combined by the shfl_xor(16) that also replicates x.
// lane = h*16 + c*8 + i; warp = one column; 16 blocks x 128 threads.

__global__ void __launch_bounds__(128, 1) lista_kernel(
    const float* __restrict__ y_real, const float* __restrict__ y_imag,
    const float* __restrict__ w1_real, const float* __restrict__ w1_imag,
    const float* __restrict__ w2_real, const float* __restrict__ w2_imag,
    const float* __restrict__ thr,
    const float* __restrict__ c1w, const float* __restrict__ c1b,
    const float* __restrict__ c2w, const float* __restrict__ c2b,
    float* __restrict__ out)
{
    __shared__ __align__(16) float s_w2r [1024];   // w2_real, 16 stages
    __shared__ __align__(16) float s_w2ip[1024];   // +w2_imag (c=1)
    __shared__ __align__(16) float s_w2in[1024];   // -w2_imag (c=0)
    // per-(stage,h) conv pack, 16 floats:
    // [0..2]=k1A, [3..5]=k1B, [6]=b1A, [7]=b1B,
    // [8..10]=k2A, [11..13]=k2B, [14]=thr, [15]=cb2 (h=0 only, else 0)
    // where chA = h?2:0, chB = h?none(zeros):1
    __shared__ __align__(16) float s_cvh[16 * 2 * 16];

    const int tid  = threadIdx.x;          // 0..127
    const int lane = tid & 31;
    const int i    = lane & 7;
    const int c    = (lane >> 3) & 1;
    const int h    = lane >> 4;
    const int b    = (int)blockIdx.x * 4 + (tid >> 5);   // batch column

    // ---- staging: W2 tables (+/- imag) ----
    {
        const float4* gr = (const float4*)w2_real;
        const float4* gi = (const float4*)w2_imag;
        #pragma unroll
        for (int k = tid; k < 256; k += 128) {
            float4 vr = gr[k];
            float4 vi = gi[k];
            ((float4*)s_w2r )[k] = vr;
            ((float4*)s_w2ip)[k] = vi;
            ((float4*)s_w2in)[k] = make_float4(-vi.x, -vi.y, -vi.z, -vi.w);
        }
    }
    // ---- per-(stage,h) conv packs ----
    #pragma unroll
    for (int k = tid; k < 512; k += 128) {
        const int s  = k >> 5;             // stage
        const int hh = (k >> 4) & 1;       // h slot
        const int r  = k & 15;
        const int chA = hh ? 2 : 0;
        float v = 0.f;
        if (r < 3)        v = c1w[s * 9 + chA * 3 + r];
        else if (r < 6)   v = hh ? 0.f : c1w[s * 9 + 3 + (r - 3)];
        else if (r == 6)  v = c1b[s * 3 + chA];
        else if (r == 7)  v = hh ? 0.f : c1b[s * 3 + 1];
        else if (r < 11)  v = c2w[s * 9 + chA * 3 + (r - 8)];
        else if (r < 14)  v = hh ? 0.f : c2w[s * 9 + 3 + (r - 11)];
        else if (r == 14) v = thr[s];
        else              v = hh ? 0.f : c2b[s];
        s_cvh[k] = v;
    }

    // ---- y half-slices (own comp + sign-folded opposite) ----
    const float sgn = c ? 1.f : -1.f;   // z_r: -wi*x_i ; z_i: +wi*x_r
    float yc[4], yos[4];
    {
        const float* yc_ptr = c ? y_imag : y_real;
        const float* yo_ptr = c ? y_real : y_imag;
        #pragma unroll
        for (int j4 = 0; j4 < 4; j4++) {
            int j = h * 4 + j4;
            yc[j4]  = yc_ptr[j * 64 + b];
            yos[j4] = sgn * yo_ptr[j * 64 + b];
        }
    }

    // ---- precompute 16 stage HALF-biases (W1[s] y), this j-half ----
    float bias[16];
    #pragma unroll
    for (int s = 0; s < 16; s++) {
        const float4 wr = *(const float4*)(w1_real + s * 64 + i * 8 + h * 4);
        const float4 wi = *(const float4*)(w1_imag + s * 64 + i * 8 + h * 4);
        float a0 = 0.f, a1 = 0.f;
        a0 = fmaf(wr.x, yc[0], a0); a1 = fmaf(wi.x, yos[0], a1);
        a0 = fmaf(wr.y, yc[1], a0); a1 = fmaf(wi.y, yos[1], a1);
        a0 = fmaf(wr.z, yc[2], a0); a1 = fmaf(wi.z, yos[2], a1);
        a0 = fmaf(wr.w, yc[3], a0); a1 = fmaf(wi.w, yos[3], a1);
        bias[s] = a0 + a1;
    }

    __syncthreads();

    // ---- static pointers (loop body: LDS [ptr + imm] only) ----
    const float* pw_r = s_w2r + i * 8 + h * 4;
    const float* pw_i = (c ? s_w2ip : s_w2in) + i * 8 + h * 4;
    const float* pcv  = s_cvh + h * 16;    // advances 32/stage
    const bool   e0 = (i > 0), e2 = (i < 7);

    // ---- init: x = soft(full bias[0], thr[0]) ----
    float x;
    {
        const float b0 = bias[0] + __shfl_xor_sync(FULL, bias[0], 16);
        const float t0 = s_cvh[14];
        x = b0 - fminf(fmaxf(b0, -t0), t0);
    }

    const int src_c = (c << 3);        // lanes holding own-comp x_j (h=0)
    const int src_o = ((c ^ 1) << 3);  // opposite comp
    const int pc    = c << 3;          // partial-fetch base (own comp)

    // ---- 16 sequential stages (fully unrolled) ----
    #pragma unroll
    for (int s = 0; s < 16; s++) {
        // wave 1: broadcast x for this thread's j-half
        float xc[4], xo[4];
        #pragma unroll
        for (int j4 = 0; j4 < 4; j4++) {
            int j = h * 4 + j4;
            xc[j4] = __shfl_sync(FULL, x, src_c + j);
            xo[j4] = __shfl_sync(FULL, x, src_o + j);
        }

        // half dot: a = half-bias + this half's W2 x contribution
        const float4 wr = *(const float4*)(pw_r + s * 64);
        const float4 wi = *(const float4*)(pw_i + s * 64);
        float a0 = bias[s], a1 = 0.f;
        a0 = fmaf(wr.x, xc[0], a0); a1 = fmaf(wi.x, xo[0], a1);
        a0 = fmaf(wr.y, xc[1], a0); a1 = fmaf(wi.y, xo[1], a1);
        a0 = fmaf(wr.z, xc[2], a0); a1 = fmaf(wi.z, xo[2], a1);
        a0 = fmaf(wr.w, xc[3], a0); a1 = fmaf(wi.w, xo[3], a1);
        const float a = a0 + a1;

        // wave 2 (merged reduce+neighbors): fetch both half partials at
        // positions i-2..i+2 and sum locally — ONE dependent wave.
        const int pm2 = pc | ((i - 2) & 7), pm1 = pc | ((i - 1) & 7);
        const int pp1 = pc | ((i + 1) & 7), pp2 = pc | ((i + 2) & 7);
        const float q0a = __shfl_sync(FULL, a, pm2);
        const float q0b = __shfl_sync(FULL, a, 16 | pm2);
        const float q1a = __shfl_sync(FULL, a, pm1);
        const float q1b = __shfl_sync(FULL, a, 16 | pm1);
        const float q2a = __shfl_sync(FULL, a, pc | i);
        const float q2b = __shfl_sync(FULL, a, 16 | pc | i);
        const float q3a = __shfl_sync(FULL, a, pp1);
        const float q3b = __shfl_sync(FULL, a, 16 | pp1);
        const float q4a = __shfl_sync(FULL, a, pp2);
        const float q4b = __shfl_sync(FULL, a, 16 | pp2);
        float zv[5];
        zv[0] = (i >= 2) ? (q0a + q0b) : 0.f;
        zv[1] = (i >= 1) ? (q1a + q1b) : 0.f;
        zv[2] = q2a + q2b;
        zv[3] = (i <= 6) ? (q3a + q3b) : 0.f;
        zv[4] = (i <= 5) ? (q4a + q4b) : 0.f;

        // per-h conv pack: 4 broadcast LDS.128 (hoistable)
        const float4 r0 = *(const float4*)(pcv + s * 32);
        const float4 r1 = *(const float4*)(pcv + s * 32 + 4);
        const float4 r2 = *(const float4*)(pcv + s * 32 + 8);
        const float4 r3 = *(const float4*)(pcv + s * 32 + 12);
        const float k1v[2][3] = {{r0.x, r0.y, r0.z}, {r0.w, r1.x, r1.y}};
        const float bbv[2]    = {r1.z, r1.w};
        const float k2v[2][3] = {{e0 ? r2.x : 0.f, r2.y, e2 ? r2.z : 0.f},
                                 {e0 ? r2.w : 0.f, r3.x, e2 ? r3.y : 0.f}};
        const float t  = r3.z;
        const float tn = -t;
        const float cb2 = r3.w;             // nonzero only on h=0

        // conv1 + 3-op soft at pos i-1,i,i+1 for THIS h's 2 channels,
        // conv2 partial; full o assembled by the xor-16 combine below.
        float o = cb2;
        #pragma unroll
        for (int ch = 0; ch < 2; ch++) {
            const float w0 = k1v[ch][0], w1 = k1v[ch][1], w2 = k1v[ch][2];
            const float bb = bbv[ch];
            float v0 = bb, v1 = bb, v2 = bb;
            v0 = fmaf(w0, zv[0], v0); v1 = fmaf(w0, zv[1], v1); v2 = fmaf(w0, zv[2], v2);
            v0 = fmaf(w1, zv[1], v0); v1 = fmaf(w1, zv[2], v1); v2 = fmaf(w1, zv[3], v2);
            v0 = fmaf(w2, zv[2], v0); v1 = fmaf(w2, zv[3], v1); v2 = fmaf(w2, zv[4], v2);
            const float s0 = v0 - fminf(fmaxf(v0, tn), t);
            const float s1 = v1 - fminf(fmaxf(v1, tn), t);
            const float s2 = v2 - fminf(fmaxf(v2, tn), t);
            o = fmaf(k2v[ch][0], s0, o);
            o = fmaf(k2v[ch][1], s1, o);
            o = fmaf(k2v[ch][2], s2, o);
        }
        // combine the two h-partials -> full x on ALL lanes
        x = o + __shfl_xor_sync(FULL, o, 16);
    }

    // out: x_r (8,64) then x_i (8,64); h=0 lanes write
    if (h == 0) out[c * 512 + i * 64 + b] = x;
}

extern "C" void kernel_launch(void* const* d_in, const int* in_sizes, int n_in,
                              void* d_out, int out_size) {
    (void)in_sizes; (void)n_in; (void)out_size;
    const float* y_real  = (const float*)d_in[0];
    const float* y_imag  = (const float*)d_in[1];
    const float* w1_real = (const float*)d_in[2];
    const float* w1_imag = (const float*)d_in[3];
    const float* w2_real = (const float*)d_in[4];
    const float* w2_imag = (const float*)d_in[5];
    const float* thr     = (const float*)d_in[6];
    const float* c1w     = (const float*)d_in[7];
    const float* c1b     = (const float*)d_in[8];
    const float* c2w     = (const float*)d_in[9];
    const float* c2b     = (const float*)d_in[10];
    float* out = (float*)d_out;

    lista_kernel<<<16, 128>>>(y_real, y_imag, w1_real, w1_imag,
                              w2_real, w2_imag, thr, c1w, c1b, c2w, c2b, out);
}